// round 2
// baseline (speedup 1.0000x reference)
#include <cuda_runtime.h>
#include <cuda_bf16.h>
#include <cstdint>

#define T_LEN 1024
#define B_N   128
#define H_N   256
#define G3    768

// ---------------- scratch (device globals; no allocations allowed) ----------
__device__ float g_xg[(size_t)T_LEN * B_N * G3];      // [t][b][768]
__device__ float g_seq[(size_t)B_N * T_LEN * H_N];    // [b][t][256] layer-1 output
__device__ float g_hlast[B_N * H_N];                  // layer-2 final hidden

// ---------------- helpers ---------------------------------------------------
__device__ __forceinline__ float sigmoidf_(float x) {
    return 1.0f / (1.0f + __expf(-x));
}
__device__ __forceinline__ float tanhf_(float x) {
    float ax = fabsf(x);
    float e  = __expf(-2.0f * ax);            // in (0,1], no overflow
    float t  = (1.0f - e) / (1.0f + e);
    return copysignf(t, x);
}

__device__ __forceinline__ void cluster_sync_() {
    asm volatile("barrier.cluster.arrive.aligned;" ::: "memory");
    asm volatile("barrier.cluster.wait.aligned;"   ::: "memory");
}
__device__ __forceinline__ void st_shared_cluster_f32(uint32_t laddr, uint32_t rank, float v) {
    uint32_t raddr;
    asm volatile("mapa.shared::cluster.u32 %0, %1, %2;" : "=r"(raddr) : "r"(laddr), "r"(rank));
    asm volatile("st.shared::cluster.f32 [%0], %1;" :: "r"(raddr), "f"(v) : "memory");
}
__device__ __forceinline__ uint32_t smem_u32(const void* p) {
    return (uint32_t)__cvta_generic_to_shared(p);
}

// ============================================================================
// Input projection GEMM:
//   g_xg[t][b][nt*64+n] = sum_k A[b][t][k] * W[nt*64+n][k] + bias[nt*64+n]
// A = x (use_gseq==0) or g_seq (use_gseq==1); both are [b][t][256] row-major.
// Tile: M=128 (all b of one t), N=64, K=256 (full depth, single-buffered).
// ============================================================================
#define GEMM_SMEM ((128*257 + 64*257) * 4)

__global__ void gemm_xg_kernel(const float* __restrict__ Ax,
                               const float* __restrict__ W,
                               const float* __restrict__ bias,
                               int use_gseq)
{
    extern __shared__ float sm[];
    float* sA = sm;               // [128][257]
    float* sB = sm + 128 * 257;   // [64][257]

    const float* A = use_gseq ? g_seq : Ax;

    const int tid = threadIdx.x;
    const int t  = blockIdx.y;
    const int nt = blockIdx.x;

    // ---- load A tile (128 rows x 256 k) ----
#pragma unroll
    for (int i = 0; i < 32; i++) {
        int lin = i * 256 + tid;
        int m   = lin >> 6;
        int c4  = (lin & 63) << 2;
        float4 v = *(const float4*)(A + ((size_t)m * T_LEN + t) * H_N + c4);
        float* d = sA + m * 257 + c4;
        d[0] = v.x; d[1] = v.y; d[2] = v.z; d[3] = v.w;
    }
    // ---- load B tile (64 W rows x 256 k) ----
#pragma unroll
    for (int i = 0; i < 16; i++) {
        int lin = i * 256 + tid;
        int n   = lin >> 6;
        int c4  = (lin & 63) << 2;
        float4 v = *(const float4*)(W + ((size_t)(nt * 64 + n)) * H_N + c4);
        float* d = sB + n * 257 + c4;
        d[0] = v.x; d[1] = v.y; d[2] = v.z; d[3] = v.w;
    }
    __syncthreads();

    const int ty = tid >> 4;   // 0..15
    const int tx = tid & 15;   // 0..15

    float acc[8][4];
#pragma unroll
    for (int j = 0; j < 8; j++)
#pragma unroll
        for (int i = 0; i < 4; i++) acc[j][i] = 0.0f;

#pragma unroll 4
    for (int k = 0; k < 256; k++) {
        float a[8], b[4];
#pragma unroll
        for (int j = 0; j < 8; j++) a[j] = sA[(ty + (j << 4)) * 257 + k];
#pragma unroll
        for (int i = 0; i < 4; i++) b[i] = sB[(tx + (i << 4)) * 257 + k];
#pragma unroll
        for (int j = 0; j < 8; j++)
#pragma unroll
            for (int i = 0; i < 4; i++) acc[j][i] += a[j] * b[i];
    }

    // ---- epilogue: + bias, write [t][b][768] ----
#pragma unroll
    for (int i = 0; i < 4; i++) {
        int n  = nt * 64 + tx + (i << 4);
        float bv = bias[n];
#pragma unroll
        for (int j = 0; j < 8; j++) {
            int m = ty + (j << 4);
            g_xg[((size_t)t * B_N + m) * G3 + n] = acc[j][i] + bv;
        }
    }
}

// ============================================================================
// GRU recurrence: persistent 4-CTA-cluster kernel.
// Cluster cl handles batch rows [4*cl, 4*cl+4); CTA rank c holds W_hh rows for
// units [64c, 64c+64) of all 3 gates, SMEM-resident, and computes those units'
// h_new for its 4 batch rows each step. h broadcast via DSMEM + cluster barrier.
// 128 threads: up = tid&31 (unit pair), ks = tid>>5 (k quarter).
// ============================================================================
#define WT_STRIDE 194
#define REC_SMEM  ((256*WT_STRIDE + 2*1024 + 3104) * 4)

__global__ void __cluster_dims__(4, 1, 1) gru_rec_kernel(
    const float* __restrict__ Whh,   // this layer's [768][256]
    const float* __restrict__ bhh,   // this layer's [768]
    int layer)
{
    extern __shared__ float sm[];
    float* sW = sm;                       // [256][WT_STRIDE] transposed weights
    float* sH = sm + 256 * WT_STRIDE;     // [2][256*4]  h double buffer, idx = ug*4+b
    float* sP = sH + 2 * 1024;            // partial staging, up*97 + ks*24 + (g*2+du)*4 + b

    const int tid  = threadIdx.x;
    const int rank = blockIdx.x & 3;
    const int b0   = (blockIdx.x >> 2) * 4;

    // ---- load transposed weight slice: sW[k][j], j = gate*64 + ulocal ----
    for (int idx = tid; idx < 192 * 256; idx += 128) {
        int j  = idx >> 8;
        int k  = idx & 255;
        int jg = ((j >> 6) << 8) + (rank << 6) + (j & 63);
        sW[k * WT_STRIDE + j] = Whh[(size_t)jg * H_N + k];
    }
    // ---- zero h buffers ----
    for (int i = tid; i < 2048; i += 128) sH[i] = 0.0f;

    // ---- per-thread output assignment (2 outputs: o1=tid, o2=tid+128) ----
    const int u1 = tid >> 2,          b1 = tid & 3;
    const int u2 = (tid + 128) >> 2,  b2 = tid & 3;   // o2 & 3 == tid & 3
    const int ug1 = (rank << 6) + u1;
    const int ug2 = (rank << 6) + u2;
    const float br1 = bhh[ug1], bz1 = bhh[256 + ug1], bn1 = bhh[512 + ug1];
    const float br2 = bhh[ug2], bz2 = bhh[256 + ug2], bn2 = bhh[512 + ug2];

    const int up = tid & 31;
    const int ks = tid >> 5;

    __syncthreads();
    cluster_sync_();

    int p = 0;
    for (int t = 0; t < T_LEN; t++) {
        // ---- prefetch this step's xg (in flight during FMA phase) ----
        size_t xb1 = ((size_t)t * B_N + b0 + b1) * G3 + ug1;
        size_t xb2 = ((size_t)t * B_N + b0 + b2) * G3 + ug2;
        float xr1 = g_xg[xb1], xz1 = g_xg[xb1 + 256], xn1 = g_xg[xb1 + 512];
        float xr2 = g_xg[xb2], xz2 = g_xg[xb2 + 256], xn2 = g_xg[xb2 + 512];

        // ---- FMA phase: partial hg for 2 units x 4 batch x 3 gates ----
        const float* hb = sH + p * 1024;
        float acc[3][2][4];
#pragma unroll
        for (int g = 0; g < 3; g++)
#pragma unroll
            for (int d = 0; d < 2; d++)
#pragma unroll
                for (int b = 0; b < 4; b++) acc[g][d][b] = 0.0f;

        const int kbase = ks << 6;
#pragma unroll 4
        for (int kk = 0; kk < 64; kk++) {
            int k = kbase + kk;
            const float* wr = sW + k * WT_STRIDE;
            float2 w0 = ((const float2*)(wr      ))[up];
            float2 w1 = ((const float2*)(wr +  64))[up];
            float2 w2 = ((const float2*)(wr + 128))[up];
            float4 h4 = *(const float4*)(hb + (k << 2));
            acc[0][0][0] += w0.x * h4.x; acc[0][0][1] += w0.x * h4.y;
            acc[0][0][2] += w0.x * h4.z; acc[0][0][3] += w0.x * h4.w;
            acc[0][1][0] += w0.y * h4.x; acc[0][1][1] += w0.y * h4.y;
            acc[0][1][2] += w0.y * h4.z; acc[0][1][3] += w0.y * h4.w;
            acc[1][0][0] += w1.x * h4.x; acc[1][0][1] += w1.x * h4.y;
            acc[1][0][2] += w1.x * h4.z; acc[1][0][3] += w1.x * h4.w;
            acc[1][1][0] += w1.y * h4.x; acc[1][1][1] += w1.y * h4.y;
            acc[1][1][2] += w1.y * h4.z; acc[1][1][3] += w1.y * h4.w;
            acc[2][0][0] += w2.x * h4.x; acc[2][0][1] += w2.x * h4.y;
            acc[2][0][2] += w2.x * h4.z; acc[2][0][3] += w2.x * h4.w;
            acc[2][1][0] += w2.y * h4.x; acc[2][1][1] += w2.y * h4.y;
            acc[2][1][2] += w2.y * h4.z; acc[2][1][3] += w2.y * h4.w;
        }

        // ---- stage partials ----
        {
            int pb = up * 97 + ks * 24;
#pragma unroll
            for (int g = 0; g < 3; g++)
#pragma unroll
                for (int d = 0; d < 2; d++)
#pragma unroll
                    for (int b = 0; b < 4; b++)
                        sP[pb + (g * 2 + d) * 4 + b] = acc[g][d][b];
        }
        __syncthreads();

        // ---- reduce + elementwise for the 2 owned outputs ----
        float hn_v1, hn_v2;
        {
            int upo = u1 >> 1, duo = u1 & 1;
            float hr = 0, hz = 0, hn = 0;
#pragma unroll
            for (int q = 0; q < 4; q++) {
                int base = upo * 97 + q * 24 + duo * 4 + b1;
                hr += sP[base];
                hz += sP[base +  8];
                hn += sP[base + 16];
            }
            hr += br1; hz += bz1; hn += bn1;
            float hold = hb[(ug1 << 2) + b1];
            float r = sigmoidf_(xr1 + hr);
            float z = sigmoidf_(xz1 + hz);
            float n = tanhf_(xn1 + r * hn);
            hn_v1 = (1.0f - z) * n + z * hold;
        }
        {
            int upo = u2 >> 1, duo = u2 & 1;
            float hr = 0, hz = 0, hn = 0;
#pragma unroll
            for (int q = 0; q < 4; q++) {
                int base = upo * 97 + q * 24 + duo * 4 + b2;
                hr += sP[base];
                hz += sP[base +  8];
                hn += sP[base + 16];
            }
            hr += br2; hz += bz2; hn += bn2;
            float hold = hb[(ug2 << 2) + b2];
            float r = sigmoidf_(xr2 + hr);
            float z = sigmoidf_(xz2 + hz);
            float n = tanhf_(xn2 + r * hn);
            hn_v2 = (1.0f - z) * n + z * hold;
        }

        // ---- broadcast h_new to all 4 cluster CTAs (incl. self) ----
        {
            float* dst = sH + (1 - p) * 1024;
            uint32_t la1 = smem_u32(dst + (ug1 << 2) + b1);
            uint32_t la2 = smem_u32(dst + (ug2 << 2) + b2);
#pragma unroll
            for (uint32_t r = 0; r < 4; r++) {
                st_shared_cluster_f32(la1, r, hn_v1);
                st_shared_cluster_f32(la2, r, hn_v2);
            }
        }

        // ---- sequence / final output ----
        if (layer == 0) {
            g_seq[((size_t)(b0 + b1) * T_LEN + t) * H_N + ug1] = hn_v1;
            g_seq[((size_t)(b0 + b2) * T_LEN + t) * H_N + ug2] = hn_v2;
        } else if (t == T_LEN - 1) {
            g_hlast[(b0 + b1) * H_N + ug1] = hn_v1;
            g_hlast[(b0 + b2) * H_N + ug2] = hn_v2;
        }

        cluster_sync_();   // publishes h_new; also separates sP phases
        p ^= 1;
    }
}

// ============================================================================
// Final FC: out[b][n] = sigmoid(dot(g_hlast[b], W_fc[n]) + b_fc[n])
// ============================================================================
__global__ void fc_kernel(const float* __restrict__ Wfc,
                          const float* __restrict__ bfc,
                          float* __restrict__ out)
{
    __shared__ float sh[H_N];
    const int b = blockIdx.x, n = threadIdx.x;
    sh[n] = g_hlast[b * H_N + n];
    __syncthreads();
    const float* w = Wfc + (size_t)n * H_N;
    float acc = 0.0f;
#pragma unroll 4
    for (int k = 0; k < H_N; k++) acc += sh[k] * w[k];
    out[b * H_N + n] = sigmoidf_(acc + bfc[n]);
}

// ============================================================================
extern "C" void kernel_launch(void* const* d_in, const int* in_sizes, int n_in,
                              void* d_out, int out_size)
{
    const float* x   = (const float*)d_in[0];
    const float* Wih = (const float*)d_in[1];
    const float* Whh = (const float*)d_in[2];
    const float* bih = (const float*)d_in[3];
    const float* bhh = (const float*)d_in[4];
    const float* Wfc = (const float*)d_in[5];
    const float* bfc = (const float*)d_in[6];
    float* out = (float*)d_out;

    cudaFuncSetAttribute(gemm_xg_kernel, cudaFuncAttributeMaxDynamicSharedMemorySize, GEMM_SMEM);
    cudaFuncSetAttribute(gru_rec_kernel, cudaFuncAttributeMaxDynamicSharedMemorySize, REC_SMEM);

    dim3 ggrid(12, T_LEN);

    // layer 0
    gemm_xg_kernel<<<ggrid, 256, GEMM_SMEM>>>(x, Wih, bih, 0);
    gru_rec_kernel<<<128, 128, REC_SMEM>>>(Whh, bhh, 0);
    // layer 1
    gemm_xg_kernel<<<ggrid, 256, GEMM_SMEM>>>(nullptr, Wih + (size_t)G3 * H_N, bih + G3, 1);
    gru_rec_kernel<<<128, 128, REC_SMEM>>>(Whh + (size_t)G3 * H_N, bhh + G3, 1);
    // head
    fc_kernel<<<B_N, H_N>>>(Wfc, bfc, out);
}

// round 3
// speedup vs baseline: 1.0209x; 1.0209x over previous
#include <cuda_runtime.h>
#include <cuda_bf16.h>
#include <cstdint>

#define T_LEN 1024
#define B_N   128
#define H_N   256
#define G3    768

// ---------------- scratch (device globals; no allocations allowed) ----------
__device__ float g_xg[(size_t)T_LEN * B_N * G3];      // [t][b][768]
__device__ float g_seq[(size_t)B_N * T_LEN * H_N];    // [b][t][256] layer-1 output
__device__ float g_hlast[B_N * H_N];                  // layer-2 final hidden

// ---------------- helpers ---------------------------------------------------
__device__ __forceinline__ float sigmoidf_(float x) {
    return 1.0f / (1.0f + __expf(-x));
}
__device__ __forceinline__ float tanhf_(float x) {
    float ax = fabsf(x);
    float e  = __expf(-2.0f * ax);            // in (0,1], no overflow
    float t  = (1.0f - e) / (1.0f + e);
    return copysignf(t, x);
}

// packed fp32x2 FMA: d = a*b + d  (lanes independent, rn)
__device__ __forceinline__ void fma2_(unsigned long long& d,
                                      unsigned long long a,
                                      unsigned long long b) {
    asm("fma.rn.f32x2 %0, %1, %2, %0;" : "+l"(d) : "l"(a), "l"(b));
}
__device__ __forceinline__ unsigned long long packrep_(float v) {
    unsigned long long r;
    asm("mov.b64 %0, {%1, %1};" : "=l"(r) : "f"(v));
    return r;
}
__device__ __forceinline__ void unpack2_(unsigned long long v, float& lo, float& hi) {
    asm("mov.b64 {%0, %1}, %2;" : "=f"(lo), "=f"(hi) : "l"(v));
}

__device__ __forceinline__ void cluster_sync_() {
    asm volatile("barrier.cluster.arrive.aligned;" ::: "memory");
    asm volatile("barrier.cluster.wait.aligned;"   ::: "memory");
}
__device__ __forceinline__ void st_shared_cluster_f32(uint32_t laddr, uint32_t rank, float v) {
    uint32_t raddr;
    asm volatile("mapa.shared::cluster.u32 %0, %1, %2;" : "=r"(raddr) : "r"(laddr), "r"(rank));
    asm volatile("st.shared::cluster.f32 [%0], %1;" :: "r"(raddr), "f"(v) : "memory");
}
__device__ __forceinline__ uint32_t smem_u32(const void* p) {
    return (uint32_t)__cvta_generic_to_shared(p);
}

// ============================================================================
// Input projection GEMM (FFMA2 version):
//   g_xg[t][b][nt*64+n] = sum_k A[b][t][k] * W[nt*64+n][k] + bias[nt*64+n]
// A tile stored TRANSPOSED in smem: sA[k][m] (stride 130) so adjacent-m pairs
// are contiguous u64 (broadcast LDS.64 per half-warp). B scalar, replicated
// into both f32x2 lanes with one mov. Accumulators packed over m-pairs.
// ============================================================================
#define SA_STRIDE 130
#define SB_STRIDE 257
#define GEMM_SMEM ((256*SA_STRIDE + 64*SB_STRIDE) * 4)

__global__ void gemm_xg_kernel(const float* __restrict__ Ax,
                               const float* __restrict__ W,
                               const float* __restrict__ bias,
                               int use_gseq)
{
    extern __shared__ float sm[];
    float* sA = sm;                       // [256 k][130]  (m index inside)
    float* sB = sm + 256 * SA_STRIDE;     // [64 n][257]

    const float* A = use_gseq ? g_seq : Ax;

    const int tid = threadIdx.x;
    const int t  = blockIdx.y;
    const int nt = blockIdx.x;

    // ---- load A tile transposed: sA[k][m] ; thread owns k=tid, loops m ----
    {
        const int k = tid;   // 0..255
        const float* src = A + (size_t)t * H_N + k;   // + m*T_LEN*H_N
        float* dst = sA + k * SA_STRIDE;
#pragma unroll 8
        for (int m = 0; m < 128; m++)
            dst[m] = src[(size_t)m * T_LEN * H_N];
    }
    // ---- load B tile (64 W rows x 256 k) ----
#pragma unroll
    for (int i = 0; i < 16; i++) {
        int lin = i * 256 + tid;
        int n   = lin >> 6;
        int c4  = (lin & 63) << 2;
        float4 v = *(const float4*)(W + ((size_t)(nt * 64 + n)) * H_N + c4);
        float* d = sB + n * SB_STRIDE + c4;
        d[0] = v.x; d[1] = v.y; d[2] = v.z; d[3] = v.w;
    }
    __syncthreads();

    const int ty = tid >> 4;   // 0..15  -> m pair base 2*ty (+32*jj)
    const int tx = tid & 15;   // 0..15  -> n = tx (+16*i)

    unsigned long long acc[4][4];   // [jj (m-block)][i (n)]
#pragma unroll
    for (int j = 0; j < 4; j++)
#pragma unroll
        for (int i = 0; i < 4; i++) acc[j][i] = 0ull;

#pragma unroll 2
    for (int k = 0; k < 256; k++) {
        const float* ak = sA + k * SA_STRIDE + 2 * ty;
        unsigned long long a0 = *(const unsigned long long*)(ak);
        unsigned long long a1 = *(const unsigned long long*)(ak + 32);
        unsigned long long a2 = *(const unsigned long long*)(ak + 64);
        unsigned long long a3 = *(const unsigned long long*)(ak + 96);
        unsigned long long b0 = packrep_(sB[(tx     ) * SB_STRIDE + k]);
        unsigned long long b1 = packrep_(sB[(tx + 16) * SB_STRIDE + k]);
        unsigned long long b2 = packrep_(sB[(tx + 32) * SB_STRIDE + k]);
        unsigned long long b3 = packrep_(sB[(tx + 48) * SB_STRIDE + k]);
        fma2_(acc[0][0], a0, b0); fma2_(acc[0][1], a0, b1);
        fma2_(acc[0][2], a0, b2); fma2_(acc[0][3], a0, b3);
        fma2_(acc[1][0], a1, b0); fma2_(acc[1][1], a1, b1);
        fma2_(acc[1][2], a1, b2); fma2_(acc[1][3], a1, b3);
        fma2_(acc[2][0], a2, b0); fma2_(acc[2][1], a2, b1);
        fma2_(acc[2][2], a2, b2); fma2_(acc[2][3], a2, b3);
        fma2_(acc[3][0], a3, b0); fma2_(acc[3][1], a3, b1);
        fma2_(acc[3][2], a3, b2); fma2_(acc[3][3], a3, b3);
    }

    // ---- epilogue: + bias, write [t][b][768] ----
#pragma unroll
    for (int i = 0; i < 4; i++) {
        int n  = nt * 64 + tx + (i << 4);
        float bv = bias[n];
#pragma unroll
        for (int j = 0; j < 4; j++) {
            int m0 = 2 * ty + (j << 5);
            float lo, hi;
            unpack2_(acc[j][i], lo, hi);
            g_xg[((size_t)t * B_N + m0    ) * G3 + n] = lo + bv;
            g_xg[((size_t)t * B_N + m0 + 1) * G3 + n] = hi + bv;
        }
    }
}

// ============================================================================
// GRU recurrence v2: persistent 4-CTA-cluster kernel, 384 threads.
// CTA rank owns 192 W_hh rows (3 gates x 64 units), SMEM-resident.
// Thread (w,l): row = w*16 + (l&15) in [0,192), kh = l>>4 (k half).
// Each thread: 1 row x 4 batches x 128 k, accumulators packed fp32x2 over
// adjacent k. 2-way k-half reduction through sP. One __syncthreads + one
// cluster.sync per step. h as [buf][b][256] (float4 loads, phase-uniform
// broadcast). Weights sW[row][258]: kh0 cols 0..127, kh1 cols 130..257
// (conflict-free LDS.64 given the lane->row/kh mapping).
// ============================================================================
#define WROW_STRIDE 258
#define KH_OFF      130
#define SP_U64_ROW  9          // u64 stride per row: [kh][b] -> kh*4 + b
#define REC_SMEM ((192*WROW_STRIDE + 2*1024 + 2*192*SP_U64_ROW) * 4)

__global__ void __cluster_dims__(4, 1, 1) gru_rec_kernel(
    const float* __restrict__ Whh,   // this layer's [768][256]
    const float* __restrict__ bhh,   // this layer's [768]
    int layer)
{
    extern __shared__ float sm[];
    float* sW = sm;                              // [192][258]
    float* sH = sm + 192 * WROW_STRIDE;          // [2][4][256]
    unsigned long long* sP =                      // [192][2 kh][4 b] packed pairs
        (unsigned long long*)(sH + 2 * 1024);

    const int tid  = threadIdx.x;               // 0..383
    const int rank = blockIdx.x & 3;
    const int b0   = (blockIdx.x >> 2) * 4;

    // ---- load weight slice: sW[row][col(k)] ----
    for (int idx = tid; idx < 192 * 256; idx += 384) {
        int row = idx >> 8;
        int k   = idx & 255;
        int jg  = ((row >> 6) << 8) + (rank << 6) + (row & 63);
        sW[row * WROW_STRIDE + ((k >> 7) * KH_OFF) + (k & 127)] =
            Whh[(size_t)jg * H_N + k];
    }
    // ---- zero h double buffer ----
    for (int i = tid; i < 2048; i += 384) sH[i] = 0.0f;

    const int wrp = tid >> 5;
    const int ln  = tid & 31;
    const int row = wrp * 16 + (ln & 15);       // 0..191
    const int kh  = ln >> 4;                    // 0 or 1

    // elementwise assignment (first 256 threads): one (u, b) each
    const int eu = tid >> 2;                    // unit local 0..63 (valid tid<256)
    const int eb = tid & 3;
    const int eug = (rank << 6) + (eu & 63);
    float br_ = 0.f, bz_ = 0.f, bn_ = 0.f;
    if (tid < 256) {
        br_ = bhh[eug]; bz_ = bhh[256 + eug]; bn_ = bhh[512 + eug];
    }

    __syncthreads();
    cluster_sync_();

    const float* wr = sW + row * WROW_STRIDE + kh * KH_OFF;

    int p = 0;
    for (int t = 0; t < T_LEN; t++) {
        // ---- prefetch this step's xg ----
        float xr = 0.f, xz = 0.f, xn = 0.f;
        if (tid < 256) {
            size_t xb = ((size_t)t * B_N + b0 + eb) * G3 + eug;
            xr = g_xg[xb]; xz = g_xg[xb + 256]; xn = g_xg[xb + 512];
        }

        // ---- FMA phase ----
        const float* hb = sH + p * 1024 + kh * 128;
        unsigned long long acc0 = 0ull, acc1 = 0ull, acc2 = 0ull, acc3 = 0ull;
#pragma unroll 8
        for (int q = 0; q < 32; q++) {
            unsigned long long wA = *(const unsigned long long*)(wr + 4 * q);
            unsigned long long wB = *(const unsigned long long*)(wr + 4 * q + 2);
            ulonglong2 h0 = *(const ulonglong2*)(hb + 4 * q);
            fma2_(acc0, wA, h0.x); fma2_(acc0, wB, h0.y);
            ulonglong2 h1 = *(const ulonglong2*)(hb + 256 + 4 * q);
            fma2_(acc1, wA, h1.x); fma2_(acc1, wB, h1.y);
            ulonglong2 h2 = *(const ulonglong2*)(hb + 512 + 4 * q);
            fma2_(acc2, wA, h2.x); fma2_(acc2, wB, h2.y);
            ulonglong2 h3 = *(const ulonglong2*)(hb + 768 + 4 * q);
            fma2_(acc3, wA, h3.x); fma2_(acc3, wB, h3.y);
        }

        // ---- stage packed partials ----
        {
            unsigned long long* d = sP + row * SP_U64_ROW + kh * 4;
            d[0] = acc0; d[1] = acc1; d[2] = acc2; d[3] = acc3;
        }
        __syncthreads();

        // ---- reduce + elementwise (first 256 threads) ----
        if (tid < 256) {
            const float2* pf = (const float2*)sP;
            int ir = eu * SP_U64_ROW + eb;
            int iz = (64 + eu) * SP_U64_ROW + eb;
            int in_ = (128 + eu) * SP_U64_ROW + eb;
            float2 r0 = pf[ir], r1 = pf[ir + 4];
            float2 z0 = pf[iz], z1 = pf[iz + 4];
            float2 n0 = pf[in_], n1 = pf[in_ + 4];
            float hr = r0.x + r0.y + r1.x + r1.y + br_;
            float hz = z0.x + z0.y + z1.x + z1.y + bz_;
            float hn = n0.x + n0.y + n1.x + n1.y + bn_;

            float hold = sH[p * 1024 + eb * 256 + eug];
            float r = sigmoidf_(xr + hr);
            float z = sigmoidf_(xz + hz);
            float n = tanhf_(xn + r * hn);
            float hnew = (1.0f - z) * n + z * hold;

            // broadcast to all 4 cluster CTAs (incl. self)
            uint32_t la = smem_u32(sH + (1 - p) * 1024 + eb * 256 + eug);
#pragma unroll
            for (uint32_t rr = 0; rr < 4; rr++)
                st_shared_cluster_f32(la, rr, hnew);

            if (layer == 0) {
                g_seq[((size_t)(b0 + eb) * T_LEN + t) * H_N + eug] = hnew;
            } else if (t == T_LEN - 1) {
                g_hlast[(b0 + eb) * H_N + eug] = hnew;
            }
        }

        cluster_sync_();   // publishes h_new; separates sP/sH phases
        p ^= 1;
    }
}

// ============================================================================
// Final FC: out[b][n] = sigmoid(dot(g_hlast[b], W_fc[n]) + b_fc[n])
// ============================================================================
__global__ void fc_kernel(const float* __restrict__ Wfc,
                          const float* __restrict__ bfc,
                          float* __restrict__ out)
{
    __shared__ float sh[H_N];
    const int b = blockIdx.x, n = threadIdx.x;
    sh[n] = g_hlast[b * H_N + n];
    __syncthreads();
    const float* w = Wfc + (size_t)n * H_N;
    float acc = 0.0f;
#pragma unroll 4
    for (int k = 0; k < H_N; k++) acc += sh[k] * w[k];
    out[b * H_N + n] = sigmoidf_(acc + bfc[n]);
}

// ============================================================================
extern "C" void kernel_launch(void* const* d_in, const int* in_sizes, int n_in,
                              void* d_out, int out_size)
{
    const float* x   = (const float*)d_in[0];
    const float* Wih = (const float*)d_in[1];
    const float* Whh = (const float*)d_in[2];
    const float* bih = (const float*)d_in[3];
    const float* bhh = (const float*)d_in[4];
    const float* Wfc = (const float*)d_in[5];
    const float* bfc = (const float*)d_in[6];
    float* out = (float*)d_out;

    cudaFuncSetAttribute(gemm_xg_kernel, cudaFuncAttributeMaxDynamicSharedMemorySize, GEMM_SMEM);
    cudaFuncSetAttribute(gru_rec_kernel, cudaFuncAttributeMaxDynamicSharedMemorySize, REC_SMEM);

    dim3 ggrid(12, T_LEN);

    // layer 0
    gemm_xg_kernel<<<ggrid, 256, GEMM_SMEM>>>(x, Wih, bih, 0);
    gru_rec_kernel<<<128, 384, REC_SMEM>>>(Whh, bhh, 0);
    // layer 1
    gemm_xg_kernel<<<ggrid, 256, GEMM_SMEM>>>(nullptr, Wih + (size_t)G3 * H_N, bih + G3, 1);
    gru_rec_kernel<<<128, 384, REC_SMEM>>>(Whh + (size_t)G3 * H_N, bhh + G3, 1);
    // head
    fc_kernel<<<B_N, H_N>>>(Wfc, bfc, out);
}

// round 4
// speedup vs baseline: 1.2475x; 1.2220x over previous
#include <cuda_runtime.h>
#include <cuda_bf16.h>
#include <cstdint>

#define T_LEN 1024
#define B_N   128
#define H_N   256
#define G3    768

// ---------------- scratch (device globals; no allocations allowed) ----------
__device__ float g_xg[(size_t)T_LEN * B_N * G3];      // [t][b][768]
__device__ float g_seq[(size_t)B_N * T_LEN * H_N];    // [b][t][256] layer-1 output
__device__ float g_hlast[B_N * H_N];                  // layer-2 final hidden

// ---------------- helpers ---------------------------------------------------
__device__ __forceinline__ float sigmoidf_(float x) {
    return __fdividef(1.0f, 1.0f + __expf(-x));
}
__device__ __forceinline__ float tanhf_(float x) {
    float ax = fabsf(x);
    float e  = __expf(-2.0f * ax);            // in (0,1], no overflow
    float t  = __fdividef(1.0f - e, 1.0f + e);
    return copysignf(t, x);
}

// packed fp32x2 FMA: d = a*b + d  (lanes independent, rn)
__device__ __forceinline__ void fma2_(unsigned long long& d,
                                      unsigned long long a,
                                      unsigned long long b) {
    asm("fma.rn.f32x2 %0, %1, %2, %0;" : "+l"(d) : "l"(a), "l"(b));
}
__device__ __forceinline__ void unpack2_(unsigned long long v, float& lo, float& hi) {
    asm("mov.b64 {%0, %1}, %2;" : "=f"(lo), "=f"(hi) : "l"(v));
}

__device__ __forceinline__ void cluster_arrive_() {
    asm volatile("barrier.cluster.arrive.aligned;" ::: "memory");
}
__device__ __forceinline__ void cluster_wait_() {
    asm volatile("barrier.cluster.wait.aligned;" ::: "memory");
}
__device__ __forceinline__ void st_shared_cluster_f32(uint32_t laddr, uint32_t rank, float v) {
    uint32_t raddr;
    asm volatile("mapa.shared::cluster.u32 %0, %1, %2;" : "=r"(raddr) : "r"(laddr), "r"(rank));
    asm volatile("st.shared::cluster.f32 [%0], %1;" :: "r"(raddr), "f"(v) : "memory");
}
__device__ __forceinline__ uint32_t smem_u32(const void* p) {
    return (uint32_t)__cvta_generic_to_shared(p);
}

// ============================================================================
// Input projection GEMM, K-packed fp32x2:
//   g_xg[t][b][nt*64+n] = sum_k A[b][t][k] * W[nt*64+n][k] + bias[n]
// Both tiles NATURAL row-major (k contiguous) -> coalesced loads, no transpose.
// acc u64: lo accumulates even k, hi odd k; halves summed in epilogue.
// Thread (tx=tid>>4, ty=tid&15): outputs m = ty+16j (8), n = tx+16i (4).
// a loads: 16 distinct m per warp -> 128B/wf; b: 2 distinct n -> broadcast.
// ============================================================================
#define SA_ST 258
#define SB_ST 258
#define GEMM_SMEM ((128*SA_ST + 64*SB_ST) * 4)

__global__ void __launch_bounds__(256, 1) gemm_xg_kernel(
    const float* __restrict__ Ax,
    const float* __restrict__ W,
    const float* __restrict__ bias,
    int use_gseq)
{
    extern __shared__ float sm[];
    float* sA = sm;                    // [128 m][258]
    float* sB = sm + 128 * SA_ST;      // [64  n][258]

    const float* A = use_gseq ? g_seq : Ax;

    const int tid = threadIdx.x;
    const int t  = blockIdx.y;
    const int nt = blockIdx.x;

    // ---- load A tile (coalesced LDG.128, contiguous STS) ----
#pragma unroll
    for (int i = 0; i < 32; i++) {
        int lin = i * 256 + tid;
        int m   = lin >> 6;
        int k4  = (lin & 63) << 2;
        float4 v = *(const float4*)(A + ((size_t)m * T_LEN + t) * H_N + k4);
        float* d = sA + m * SA_ST + k4;
        *(float2*)(d)     = make_float2(v.x, v.y);
        *(float2*)(d + 2) = make_float2(v.z, v.w);
    }
    // ---- load B tile ----
#pragma unroll
    for (int i = 0; i < 16; i++) {
        int lin = i * 256 + tid;
        int n   = lin >> 6;
        int k4  = (lin & 63) << 2;
        float4 v = *(const float4*)(W + ((size_t)(nt * 64 + n)) * H_N + k4);
        float* d = sB + n * SB_ST + k4;
        *(float2*)(d)     = make_float2(v.x, v.y);
        *(float2*)(d + 2) = make_float2(v.z, v.w);
    }
    __syncthreads();

    const int tx = tid >> 4;   // 0..15 -> n = tx + 16i
    const int ty = tid & 15;   // 0..15 -> m = ty + 16j

    unsigned long long acc[8][4];
#pragma unroll
    for (int j = 0; j < 8; j++)
#pragma unroll
        for (int i = 0; i < 4; i++) acc[j][i] = 0ull;

#pragma unroll 4
    for (int kq = 0; kq < 128; kq++) {
        unsigned long long a[8], b[4];
#pragma unroll
        for (int j = 0; j < 8; j++)
            a[j] = *(const unsigned long long*)(sA + (ty + (j << 4)) * SA_ST + 2 * kq);
#pragma unroll
        for (int i = 0; i < 4; i++)
            b[i] = *(const unsigned long long*)(sB + (tx + (i << 4)) * SB_ST + 2 * kq);
#pragma unroll
        for (int j = 0; j < 8; j++)
#pragma unroll
            for (int i = 0; i < 4; i++) fma2_(acc[j][i], a[j], b[i]);
    }

    // ---- epilogue: sum halves, + bias, write [t][b][768] ----
#pragma unroll
    for (int i = 0; i < 4; i++) {
        int n  = nt * 64 + tx + (i << 4);
        float bv = bias[n];
#pragma unroll
        for (int j = 0; j < 8; j++) {
            int m = ty + (j << 4);
            float lo, hi;
            unpack2_(acc[j][i], lo, hi);
            g_xg[((size_t)t * B_N + m) * G3 + n] = lo + hi + bv;
        }
    }
}

// ============================================================================
// GRU recurrence v3: persistent 4-CTA-cluster kernel, 384 threads.
// CTA rank owns 192 W_hh rows (3 gates x 64 units). Half the weights (k-local
// 0..63 of each thread's 128-k slice) live in REGISTERS for the whole kernel;
// the other half in SMEM. Thread (w,l): row = w*16+(l&15), kh = l>>4.
// Per step: 1 row x 4 batches x 128 k, acc packed fp32x2 over adjacent k.
// Split cluster barrier: wait at loop top, arrive right after DSMEM stores.
// ============================================================================
#define WROW_ST 130          // smem weight row stride (floats): kh0 @0, kh1 @66
#define KH_OFF  66
#define SP_U64_ROW 9
#define REC_SMEM ((192*WROW_ST + 2*1024 + 2*192*SP_U64_ROW) * 4)

__global__ void __cluster_dims__(4, 1, 1) __launch_bounds__(384, 1)
gru_rec_kernel(const float* __restrict__ Whh,   // this layer's [768][256]
               const float* __restrict__ bhh,   // this layer's [768]
               int layer)
{
    extern __shared__ float sm[];
    float* sW = sm;                              // [192][130]: k-local 64..127
    float* sH = sm + 192 * WROW_ST;              // [2][4][256]
    unsigned long long* sP =                     // [192][2 kh][4 b] packed pairs
        (unsigned long long*)(sH + 2 * 1024);

    const int tid  = threadIdx.x;               // 0..383
    const int rank = blockIdx.x & 3;
    const int b0   = (blockIdx.x >> 2) * 4;

    const int wrp = tid >> 5;
    const int ln  = tid & 31;
    const int row = wrp * 16 + (ln & 15);       // 0..191
    const int kh  = ln >> 4;                    // 0 or 1
    const int jg  = ((row >> 6) << 8) + (rank << 6) + (row & 63); // global W row

    // ---- registers: k-global [kh*128, kh*128+64) as 32 u64 pairs ----
    unsigned long long wreg[32];
    {
        const float* wp = Whh + (size_t)jg * H_N + kh * 128;
#pragma unroll
        for (int j = 0; j < 32; j++)
            wreg[j] = *(const unsigned long long*)(wp + 2 * j);
    }
    // ---- SMEM: k-global [kh*128+64, kh*128+128) ----
    for (int idx = tid; idx < 192 * 128; idx += 384) {
        int r   = idx >> 7;
        int kl  = idx & 127;                    // 0..127
        int khh = kl >> 6;                      // which half
        int off = kl & 63;
        int rg  = ((r >> 6) << 8) + (rank << 6) + (r & 63);
        sW[r * WROW_ST + khh * KH_OFF + off] =
            Whh[(size_t)rg * H_N + khh * 128 + 64 + off];
    }
    // ---- zero h double buffer ----
    for (int i = tid; i < 2048; i += 384) sH[i] = 0.0f;

    // elementwise assignment (first 256 threads): one (u, b) each
    const int eu  = tid >> 2;                   // 0..63 (valid tid<256)
    const int eb  = tid & 3;
    const int eug = (rank << 6) + (eu & 63);
    float br_ = 0.f, bz_ = 0.f, bn_ = 0.f;
    if (tid < 256) {
        br_ = bhh[eug]; bz_ = bhh[256 + eug]; bn_ = bhh[512 + eug];
    }

    __syncthreads();
    cluster_arrive_();
    cluster_wait_();

    const float* wsm = sW + row * WROW_ST + kh * KH_OFF;

    int p = 0;
    for (int t = 0; t < T_LEN; t++) {
        if (t > 0) cluster_wait_();             // h[p] published by all peers

        // ---- prefetch this step's xg ----
        float xr = 0.f, xz = 0.f, xn = 0.f;
        if (tid < 256) {
            size_t xb = ((size_t)t * B_N + b0 + eb) * G3 + eug;
            xr = g_xg[xb]; xz = g_xg[xb + 256]; xn = g_xg[xb + 512];
        }

        // ---- FMA phase ----
        const float* hb = sH + p * 1024 + kh * 128;
        unsigned long long acc0 = 0ull, acc1 = 0ull, acc2 = 0ull, acc3 = 0ull;
        // k-local 0..63: weights from registers
#pragma unroll
        for (int q = 0; q < 16; q++) {
            unsigned long long wA = wreg[2 * q];
            unsigned long long wB = wreg[2 * q + 1];
            ulonglong2 h0 = *(const ulonglong2*)(hb + 4 * q);
            fma2_(acc0, wA, h0.x); fma2_(acc0, wB, h0.y);
            ulonglong2 h1 = *(const ulonglong2*)(hb + 256 + 4 * q);
            fma2_(acc1, wA, h1.x); fma2_(acc1, wB, h1.y);
            ulonglong2 h2 = *(const ulonglong2*)(hb + 512 + 4 * q);
            fma2_(acc2, wA, h2.x); fma2_(acc2, wB, h2.y);
            ulonglong2 h3 = *(const ulonglong2*)(hb + 768 + 4 * q);
            fma2_(acc3, wA, h3.x); fma2_(acc3, wB, h3.y);
        }
        // k-local 64..127: weights from SMEM
#pragma unroll
        for (int q = 0; q < 16; q++) {
            unsigned long long wA = *(const unsigned long long*)(wsm + 4 * q);
            unsigned long long wB = *(const unsigned long long*)(wsm + 4 * q + 2);
            ulonglong2 h0 = *(const ulonglong2*)(hb + 64 + 4 * q);
            fma2_(acc0, wA, h0.x); fma2_(acc0, wB, h0.y);
            ulonglong2 h1 = *(const ulonglong2*)(hb + 320 + 4 * q);
            fma2_(acc1, wA, h1.x); fma2_(acc1, wB, h1.y);
            ulonglong2 h2 = *(const ulonglong2*)(hb + 576 + 4 * q);
            fma2_(acc2, wA, h2.x); fma2_(acc2, wB, h2.y);
            ulonglong2 h3 = *(const ulonglong2*)(hb + 832 + 4 * q);
            fma2_(acc3, wA, h3.x); fma2_(acc3, wB, h3.y);
        }

        // ---- stage packed partials ----
        {
            unsigned long long* d = sP + row * SP_U64_ROW + kh * 4;
            d[0] = acc0; d[1] = acc1; d[2] = acc2; d[3] = acc3;
        }
        __syncthreads();

        // ---- reduce + elementwise (first 256 threads) ----
        float hnew = 0.f;
        if (tid < 256) {
            const float2* pf = (const float2*)sP;
            int ir  = eu * SP_U64_ROW + eb;
            int iz  = (64 + eu) * SP_U64_ROW + eb;
            int in_ = (128 + eu) * SP_U64_ROW + eb;
            float2 r0 = pf[ir],  r1 = pf[ir + 4];
            float2 z0 = pf[iz],  z1 = pf[iz + 4];
            float2 n0 = pf[in_], n1 = pf[in_ + 4];
            float hr = r0.x + r0.y + r1.x + r1.y + br_;
            float hz = z0.x + z0.y + z1.x + z1.y + bz_;
            float hn = n0.x + n0.y + n1.x + n1.y + bn_;

            float hold = sH[p * 1024 + eb * 256 + eug];
            float r = sigmoidf_(xr + hr);
            float z = sigmoidf_(xz + hz);
            float n = tanhf_(xn + r * hn);
            hnew = (1.0f - z) * n + z * hold;

            // broadcast to all 4 cluster CTAs (incl. self)
            uint32_t la = smem_u32(sH + (1 - p) * 1024 + eb * 256 + eug);
#pragma unroll
            for (uint32_t rr = 0; rr < 4; rr++)
                st_shared_cluster_f32(la, rr, hnew);
        }

        cluster_arrive_();   // release: publishes DSMEM h stores + frees sH[p]/sP

        // global stores off the critical path
        if (tid < 256) {
            if (layer == 0) {
                g_seq[((size_t)(b0 + eb) * T_LEN + t) * H_N + eug] = hnew;
            } else if (t == T_LEN - 1) {
                g_hlast[(b0 + eb) * H_N + eug] = hnew;
            }
        }
        p ^= 1;
    }
    cluster_wait_();   // don't exit while peers' DSMEM stores may be in flight
}

// ============================================================================
// Final FC: out[b][n] = sigmoid(dot(g_hlast[b], W_fc[n]) + b_fc[n])
// ============================================================================
__global__ void fc_kernel(const float* __restrict__ Wfc,
                          const float* __restrict__ bfc,
                          float* __restrict__ out)
{
    __shared__ float sh[H_N];
    const int b = blockIdx.x, n = threadIdx.x;
    sh[n] = g_hlast[b * H_N + n];
    __syncthreads();
    const float* w = Wfc + (size_t)n * H_N;
    float acc = 0.0f;
#pragma unroll 4
    for (int k = 0; k < H_N; k++) acc += sh[k] * w[k];
    out[b * H_N + n] = sigmoidf_(acc + bfc[n]);
}

// ============================================================================
extern "C" void kernel_launch(void* const* d_in, const int* in_sizes, int n_in,
                              void* d_out, int out_size)
{
    const float* x   = (const float*)d_in[0];
    const float* Wih = (const float*)d_in[1];
    const float* Whh = (const float*)d_in[2];
    const float* bih = (const float*)d_in[3];
    const float* bhh = (const float*)d_in[4];
    const float* Wfc = (const float*)d_in[5];
    const float* bfc = (const float*)d_in[6];
    float* out = (float*)d_out;

    cudaFuncSetAttribute(gemm_xg_kernel, cudaFuncAttributeMaxDynamicSharedMemorySize, GEMM_SMEM);
    cudaFuncSetAttribute(gru_rec_kernel, cudaFuncAttributeMaxDynamicSharedMemorySize, REC_SMEM);

    dim3 ggrid(12, T_LEN);

    // layer 0
    gemm_xg_kernel<<<ggrid, 256, GEMM_SMEM>>>(x, Wih, bih, 0);
    gru_rec_kernel<<<128, 384, REC_SMEM>>>(Whh, bhh, 0);
    // layer 1
    gemm_xg_kernel<<<ggrid, 256, GEMM_SMEM>>>(nullptr, Wih + (size_t)G3 * H_N, bih + G3, 1);
    gru_rec_kernel<<<128, 384, REC_SMEM>>>(Whh + (size_t)G3 * H_N, bhh + G3, 1);
    // head
    fc_kernel<<<B_N, H_N>>>(Wfc, bfc, out);
}